// round 15
// baseline (speedup 1.0000x reference)
#include <cuda_runtime.h>
#include <cuda_bf16.h>

typedef unsigned int u32;
typedef unsigned long long u64;
typedef unsigned char u8;

#define HH 512
#define NS_ 376
#define NA_ 17
#define DD 393
#define TSTEPS 8

#if defined(__CUDA_ARCH_FEAT_SM100_ALL) || defined(__CUDA_ARCH_FEAT_SM103_ALL)
#define HAS_TC 1
#else
#define HAS_TC 0
#endif

// ------------------------- scratch (device globals) -------------------------
__device__ int           g_use_tc;
__device__ u8            g_masks[2][4096][HH];            // [br][row][k] spike bitmasks (bit t)
// pre-swizzled B tiles: [br][nslice][kchunk][split] -> 32KB SW128 smem image
__device__ __nv_bfloat16 g_w2tiles[2][2][8][3][16384];
__device__ float         g_qpart[2][2][4096];             // [br][nslice][row]

// ============================ probe ============================
__global__ void probe_kernel() {
#if HAS_TC
    g_use_tc = 1;
#else
    g_use_tc = 0;
#endif
}

// ============================ K0: W2 -> bf16 3-way split, pre-swizzled tiles ============================
__global__ void prep_w2_kernel(const float* __restrict__ W2a, const float* __restrict__ W2b)
{
    if (!g_use_tc) return;
    int idx = blockIdx.x * blockDim.x + threadIdx.x;   // 0 .. 524287
    const int kq = idx & 63;
    const int nq = (idx >> 6) & 255;
    const int kc = (idx >> 14) & 7;
    const int ns = (idx >> 17) & 1;
    const int br = idx >> 18;
    const int n = ns * 256 + nq;
    const int k = kc * 64 + kq;
    const float* W2 = br ? W2b : W2a;
    float w = W2[(size_t)k * HH + n];
    __nv_bfloat16 b0 = __float2bfloat16(w);
    float r1 = w - __bfloat162float(b0);
    __nv_bfloat16 b1 = __float2bfloat16(r1);
    float r2 = r1 - __bfloat162float(b1);
    __nv_bfloat16 b2 = __float2bfloat16(r2);
    u32 off = (u32)(nq * 128 + kq * 2);
    off ^= (off >> 3) & 0x70u;
    const u32 e = off >> 1;
    g_w2tiles[br][ns][kc][0][e] = b0;
    g_w2tiles[br][ns][kc][1][e] = b1;
    g_w2tiles[br][ns][kc][2][e] = b2;
}

// ============================ K1: phase1 GEMM + IF masks (tc path) ============================
#define TM1 64
#define KB1 16

__global__ void __launch_bounds__(512, 1)
mask_kernel(const float* __restrict__ state, const float* __restrict__ action,
            const float* __restrict__ W1a, const float* __restrict__ b1a,
            const float* __restrict__ W1b, const float* __restrict__ b1b)
{
    if (!g_use_tc) return;
    __shared__ float Wbuf[KB1 * HH];
    __shared__ float Xs[KB1 * TM1];

    const int tid = threadIdx.x;
    const int rg  = tid >> 6;
    const int ci  = tid & 63;
    const int bx  = blockIdx.x;
    const int br  = bx & 1;
    const int m0  = (bx >> 1) * TM1;

    const float* W1g = br ? W1b : W1a;
    const float* b1g = br ? b1b : b1a;

    u64 acc[8][4];
    #pragma unroll
    for (int r = 0; r < 8; ++r)
        #pragma unroll
        for (int j = 0; j < 4; ++j) acc[r][j] = 0ull;

    const int NCH1 = (DD + KB1 - 1) / KB1;
    for (int kb = 0; kb < NCH1; ++kb) {
        const int k0 = kb * KB1;
        #pragma unroll
        for (int q = 0; q < 4; ++q) {
            int idx = q * 2048 + tid * 4;
            int kk = idx >> 9;
            float4 v = make_float4(0.f, 0.f, 0.f, 0.f);
            if (k0 + kk < DD)
                v = *(const float4*)(W1g + (size_t)(k0 + kk) * HH + (idx & 511));
            *(float4*)(Wbuf + idx) = v;
        }
        #pragma unroll
        for (int q = 0; q < 2; ++q) {
            int e = tid * 2 + q;
            int r = e >> 4, kk = e & 15;
            int k = k0 + kk;
            float x = 0.f;
            if (k < NS_)      x = state[(size_t)(m0 + r) * NS_ + k];
            else if (k < DD)  x = action[(size_t)(m0 + r) * NA_ + (k - NS_)];
            Xs[kk * TM1 + r] = x;
        }
        __syncthreads();
        const int kc = (DD - k0 < KB1) ? (DD - k0) : KB1;
        #pragma unroll 4
        for (int kk = 0; kk < kc; ++kk) {
            const float4 xa = *(const float4*)(Xs + kk * TM1 + rg * 8);
            const float4 xb = *(const float4*)(Xs + kk * TM1 + rg * 8 + 4);
            u64 w[4];
            #pragma unroll
            for (int j = 0; j < 4; ++j)
                w[j] = *(const u64*)(Wbuf + kk * HH + 2 * ci + 128 * j);
            const float xr[8] = {xa.x, xa.y, xa.z, xa.w, xb.x, xb.y, xb.z, xb.w};
            #pragma unroll
            for (int r = 0; r < 8; ++r) {
                u64 xp;
                asm("mov.b64 %0, {%1, %1};" : "=l"(xp) : "f"(xr[r]));
                #pragma unroll
                for (int j = 0; j < 4; ++j)
                    asm("fma.rn.f32x2 %0, %1, %2, %0;" : "+l"(acc[r][j]) : "l"(xp), "l"(w[j]));
            }
        }
        __syncthreads();
    }

    #pragma unroll
    for (int j = 0; j < 4; ++j) {
        float2 b1j = *(const float2*)(b1g + 2 * ci + 128 * j);
        #pragma unroll
        for (int h = 0; h < 2; ++h) {
            const int c = 2 * ci + 128 * j + h;
            #pragma unroll
            for (int r = 0; r < 8; ++r) {
                float hv = (h ? __uint_as_float((u32)(acc[r][j] >> 32))
                              : __uint_as_float((u32)acc[r][j]))
                         + (h ? b1j.y : b1j.x);
                float v = 0.f; u32 mb = 0u;
                #pragma unroll
                for (int t = 0; t < TSTEPS; ++t) {
                    v += hv;
                    if (v >= 1.0f) { mb |= (1u << t); v = 0.f; }
                }
                g_masks[br][m0 + rg * 8 + r][c] = (u8)mb;
            }
        }
    }
}

// ============================ K2: tcgen05 GEMM — split-granular pipeline ============================
#define MMA_IDESC 0x8400490u

#define ABASE    0          /* A tiles: [cpar][t] 16KB -> 64KB */
#define BSL_OFF  65536      /* 3 B slots x 32KB = 96KB */
#define B2_OFF   163840
#define W3_OFF   164864
#define TP_OFF   165888
#define MB_OFF   165896     /* MMA commit mbarrier (single, alternating parity) */
#define LDMB_OFF 165904     /* 3 load mbarriers (8B each) */
#define K2_SMEM  165952

#define DESC_BASE ((2ull << 61) | (1ull << 46) | (64ull << 32) | (1ull << 16))

#if HAS_TC
__device__ __forceinline__ u32 elect1() {
    u32 p;
    asm volatile("{\n\t.reg .pred p;\n\telect.sync _|p, 0xFFFFFFFF;\n\tselp.b32 %0, 1, 0, p;\n\t}" : "=r"(p));
    return p;
}
__device__ __forceinline__ void mma_f16_ss(u32 d, u64 ad, u64 bd, u32 idesc, u32 en) {
    asm volatile(
        "{\n\t.reg .pred p;\n\tsetp.ne.u32 p, %4, 0;\n\t"
        "tcgen05.mma.cta_group::1.kind::f16 [%0], %1, %2, %3, {%5, %5, %5, %5}, p;\n\t}"
        :: "r"(d), "l"(ad), "l"(bd), "r"(idesc), "r"(en), "r"(0u) : "memory");
}
__device__ __forceinline__ void mbar_wait_bounded(u32 addr, u32 parity) {
    for (int it = 0; it < (1 << 22); ++it) {
        u32 done;
        asm volatile(
            "{\n\t.reg .pred p;\n\t"
            "mbarrier.try_wait.parity.acquire.cta.shared::cta.b64 p, [%1], %2;\n\t"
            "selp.b32 %0, 1, 0, p;\n\t}"
            : "=r"(done) : "r"(addr), "r"(parity) : "memory");
        if (done) return;
    }
}
__device__ __forceinline__ void issue_bulk_tile(u32 dst, const __nv_bfloat16* src, u32 mbar) {
    asm volatile("mbarrier.arrive.expect_tx.shared.b64 _, [%0], %1;"
                 :: "r"(mbar), "r"(32768u) : "memory");
    asm volatile(
        "cp.async.bulk.shared::cta.global.mbarrier::complete_tx::bytes [%0], [%1], %2, [%3];"
        :: "r"(dst), "l"(src), "r"(32768u), "r"(mbar) : "memory");
}
#endif

__global__ void __launch_bounds__(512, 1)
gemm_scan_kernel(const float* __restrict__ b2a, const float* __restrict__ b2b,
                 const float* __restrict__ W3a, const float* __restrict__ W3b)
{
#if HAS_TC
    if (!g_use_tc) return;
    extern __shared__ char sm[];
    const u32 smb = (u32)__cvta_generic_to_shared(sm);

    const int tid = threadIdx.x;
    const int wid = tid >> 5;
    const int lid = tid & 31;
    const int sub = wid & 3;
    const int cs  = wid >> 2;
    const int bx  = blockIdx.x;
    const int br  = bx & 1;
    const int ns  = (bx >> 1) & 1;
    const int mt  = bx >> 2;
    const int m0  = mt * 128;
    const int n0  = ns * 256;

    if (wid == 0)
        asm volatile("tcgen05.alloc.cta_group::1.sync.aligned.shared::cta.b32 [%0], %1;"
                     :: "r"(smb + TP_OFF), "r"(512u) : "memory");
    else
        asm volatile("tcgen05.relinquish_alloc_permit.cta_group::1.sync.aligned;");

    const float* b2g = br ? b2b : b2a;
    const float* w3g = br ? W3b : W3a;
    float* b2s = (float*)(sm + B2_OFF);
    float* w3s = (float*)(sm + W3_OFF);
    if (tid < 256) {
        b2s[tid] = b2g[n0 + tid];
        w3s[tid] = w3g[n0 + tid];
    }
    if (tid == 0) {
        asm volatile("mbarrier.init.shared.b64 [%0], 1;" :: "r"(smb + MB_OFF) : "memory");
        #pragma unroll
        for (int s = 0; s < 3; ++s)
            asm volatile("mbarrier.init.shared.b64 [%0], 1;" :: "r"(smb + LDMB_OFF + s * 8) : "memory");
    }
    __syncthreads();

    u32 tmem;
    asm volatile("ld.shared.b32 %0, [%1];" : "=r"(tmem) : "r"(smb + TP_OFF));

    float v2[64];
    #pragma unroll
    for (int i = 0; i < 64; ++i) v2[i] = 0.f;
    float dv = 0.f;
    float cw = 0.00390625f;   // 2^-8
    int mmp = 0;              // MMA mbarrier parity (single barrier, one outstanding commit)
    int ldp[3] = {0, 0, 0};   // per-slot load parities (static-indexed via unroll)
    int skipw = 1;            // job 0 has no M(-1) to wait on

    const int arow = tid >> 2;
    const int apart = tid & 3;
    const u8* mbase = &g_masks[br][m0 + arow][0];

    // prologue: L(0)->slot0 (chunk0,split0), L(1)->slot1 (chunk0,split1)
    if (tid == 0) {
        issue_bulk_tile(smb + BSL_OFF,         &g_w2tiles[br][ns][0][0][0], smb + LDMB_OFF);
        issue_bulk_tile(smb + BSL_OFF + 32768, &g_w2tiles[br][ns][0][1][0], smb + LDMB_OFF + 8);
    }

    for (int cj = 0; cj < 32; ++cj) {
        const int kc = cj & 7;
        const int tp = cj >> 3;
        const int t0 = tp * 2;
        const int t1 = t0 + 1;
        const int cpar = cj & 1;
        const int k0 = kc * 64;
        const u32 abase = smb + (u32)cpar * 32768u;

        // ---- build A tiles for t0/t1 of this chunk (A buffer cpar; chunk cj-2 MMAs proven done) ----
        {
            const u64 m8a = *(const u64*)(mbase + k0 + apart * 16);
            const u64 m8b = *(const u64*)(mbase + k0 + apart * 16 + 8);
            #pragma unroll
            for (int p = 0; p < 8; ++p) {
                const u64 src = (p < 4) ? m8a : m8b;
                const int pp = p & 3;
                const u32 be = (u32)(src >> (16 * pp)) & 0xffu;
                const u32 bo = (u32)(src >> (16 * pp + 8)) & 0xffu;
                u32 off = (u32)(arow * 128 + (apart * 16 + 2 * p) * 2);
                off ^= (off >> 3) & 0x70u;
                const u32 v0 = (((be >> t0) & 1u) * 0x3f80u)
                             | ((((bo >> t0) & 1u) * 0x3f80u) << 16);
                const u32 v1 = (((be >> t1) & 1u) * 0x3f80u)
                             | ((((bo >> t1) & 1u) * 0x3f80u) << 16);
                *(u32*)(sm + (abase - smb) + off) = v0;
                *(u32*)(sm + (abase - smb) + 16384 + off) = v1;
            }
        }
        asm volatile("fence.proxy.async.shared::cta;" ::: "memory");
        __syncthreads();

        const u64 aD0 = DESC_BASE | (((u64)(abase >> 4)) & 0x3FFF);
        const u64 aD1 = DESC_BASE | (((u64)((abase + 16384u) >> 4)) & 0x3FFF);

        #pragma unroll
        for (int sj = 0; sj < 3; ++sj) {
            // ---- wait M(j-1): frees B slot (sj+2)%3 and throttles pipeline ----
            if (!skipw) { mbar_wait_bounded(smb + MB_OFF, (u32)mmp); mmp ^= 1; }
            else skipw = 0;

            // ---- prefetch L(j+2) ----
            if (tid == 0) {
                if (sj == 0) {
                    // L(3cj+2): chunk cj, split 2 -> slot 2
                    issue_bulk_tile(smb + BSL_OFF + 2u * 32768u,
                                    &g_w2tiles[br][ns][kc][2][0], smb + LDMB_OFF + 16);
                } else if (sj == 1 && cj < 31) {
                    // L(3cj+3): chunk cj+1, split 0 -> slot 0
                    issue_bulk_tile(smb + BSL_OFF,
                                    &g_w2tiles[br][ns][(cj + 1) & 7][0][0], smb + LDMB_OFF);
                } else if (sj == 2 && cj < 31) {
                    // L(3cj+4): chunk cj+1, split 1 -> slot 1
                    issue_bulk_tile(smb + BSL_OFF + 32768u,
                                    &g_w2tiles[br][ns][(cj + 1) & 7][1][0], smb + LDMB_OFF + 8);
                }
            }

            // ---- wait L(j) (slot sj) ----
            mbar_wait_bounded(smb + LDMB_OFF + sj * 8, (u32)ldp[sj]);
            ldp[sj] ^= 1;

            // ---- M(j): 8 MMAs (2 timesteps x 4 ksteps) with split sj, then commit ----
            if (wid == 0 && elect1()) {
                const u64 bD = DESC_BASE | (((u64)((smb + BSL_OFF + (u32)sj * 32768u) >> 4)) & 0x3FFF);
                #pragma unroll
                for (int ks = 0; ks < 4; ++ks) {
                    const u32 enf = (kc > 0 || ks > 0 || sj > 0) ? 1u : 0u;
                    mma_f16_ss(tmem,       aD0 + ks * 2, bD + ks * 2, MMA_IDESC, enf);
                    mma_f16_ss(tmem + 256, aD1 + ks * 2, bD + ks * 2, MMA_IDESC, enf);
                }
                asm volatile(
                    "tcgen05.commit.cta_group::1.mbarrier::arrive::one.shared::cluster.b64 [%0];"
                    :: "r"(smb + MB_OFF) : "memory");
            }
        }

        // ---- end of K sweep for this timestep pair: wait last job, scan both timesteps ----
        if (kc == 7) {
            mbar_wait_bounded(smb + MB_OFF, (u32)mmp); mmp ^= 1;
            skipw = 1;   // next job must not re-wait this commit
            asm volatile("tcgen05.fence::after_thread_sync;" ::: "memory");
            const int c0 = cs * 64;
            #pragma unroll
            for (int dsel = 0; dsel < 2; ++dsel) {
                #pragma unroll
                for (int h = 0; h < 2; ++h) {
                    u32 p[32];
                    asm volatile(
                        "tcgen05.ld.sync.aligned.32x32b.x32.b32 "
                        "{%0, %1, %2, %3, %4, %5, %6, %7, "
                        " %8, %9, %10, %11, %12, %13, %14, %15, "
                        " %16, %17, %18, %19, %20, %21, %22, %23, "
                        " %24, %25, %26, %27, %28, %29, %30, %31}, [%32];"
                        : "=r"(p[0]), "=r"(p[1]), "=r"(p[2]), "=r"(p[3]),
                          "=r"(p[4]), "=r"(p[5]), "=r"(p[6]), "=r"(p[7]),
                          "=r"(p[8]), "=r"(p[9]), "=r"(p[10]), "=r"(p[11]),
                          "=r"(p[12]), "=r"(p[13]), "=r"(p[14]), "=r"(p[15]),
                          "=r"(p[16]), "=r"(p[17]), "=r"(p[18]), "=r"(p[19]),
                          "=r"(p[20]), "=r"(p[21]), "=r"(p[22]), "=r"(p[23]),
                          "=r"(p[24]), "=r"(p[25]), "=r"(p[26]), "=r"(p[27]),
                          "=r"(p[28]), "=r"(p[29]), "=r"(p[30]), "=r"(p[31])
                        : "r"(tmem + dsel * 256 + c0 + 32 * h));
                    asm volatile("tcgen05.wait::ld.sync.aligned;" ::: "memory");
                    #pragma unroll
                    for (int j = 0; j < 32; ++j) {
                        const int col = c0 + 32 * h + j;
                        float val = v2[h * 32 + j] + __uint_as_float(p[j]) + b2s[col];
                        if (val >= 1.0f) { dv = fmaf(cw, w3s[col], dv); val = 0.f; }
                        v2[h * 32 + j] = val;
                    }
                }
                cw *= 2.0f;
            }
            asm volatile("tcgen05.fence::before_thread_sync;" ::: "memory");
            __syncthreads();
        }
    }

    // ---- dv reduction (dvp aliases A-tile space; MMAs all complete) ----
    float* dvp = (float*)(sm + ABASE);   // [4][128]
    dvp[cs * 128 + sub * 32 + lid] = dv;
    __syncthreads();
    if (tid < 128) {
        float s = dvp[tid] + dvp[128 + tid] + dvp[256 + tid] + dvp[384 + tid];
        g_qpart[br][ns][m0 + tid] = s;
    }
    __syncthreads();
    if (wid == 0)
        asm volatile("tcgen05.dealloc.cta_group::1.sync.aligned.b32 %0, %1;"
                     :: "r"(tmem), "r"(512u));
#else
    return;
#endif
}

// ============================ K3: combine partials ============================
__global__ void finish_kernel(const float* __restrict__ b3a, const float* __restrict__ b3b,
                              float* __restrict__ outp)
{
    if (!g_use_tc) return;
    int idx = blockIdx.x * blockDim.x + threadIdx.x;
    int br = idx >> 12;
    int b = idx & 4095;
    float b3 = (br ? b3b : b3a)[0];
    outp[idx] = g_qpart[br][0][b] + g_qpart[br][1][b] + b3 * (255.0f / 256.0f);
}

// ============================ fallback: round-8 proven sparse kernel ============================
#define TM 64
#define NTHREADS 512
#define KB2 32
#define NCH2 (HH / KB2)
#define WBUF_FLOATS (KB2 * HH)

#define SMEM_MASKB_OFF (2 * WBUF_FLOATS * 4)
#define SMEM_PLANE_OFF (SMEM_MASKB_OFF + TM * HH)
#define SMEM_XS_OFF    SMEM_PLANE_OFF
#define SMEM_RED_OFF   (SMEM_PLANE_OFF + TSTEPS * TM * 16 * 4)
#define SMEM_TOTAL_FB  (SMEM_RED_OFF + TM * 4)

__device__ __forceinline__ void ffma2(u64 &d, u64 a, u64 b) {
    asm("fma.rn.f32x2 %0, %1, %2, %0;" : "+l"(d) : "l"(a), "l"(b));
}
__device__ __forceinline__ void add2(u64 &d, u64 w) {
    asm("add.rn.f32x2 %0, %0, %1;" : "+l"(d) : "l"(w));
}
__device__ __forceinline__ u64 splat2(float x) {
    u64 r; asm("mov.b64 %0, {%1, %1};" : "=l"(r) : "f"(x)); return r;
}
__device__ __forceinline__ float lo32(u64 v) { return __uint_as_float((u32)v); }
__device__ __forceinline__ float hi32(u64 v) { return __uint_as_float((u32)(v >> 32)); }
__device__ __forceinline__ u64 pack2(float lo, float hi) {
    return (u64)__float_as_uint(lo) | ((u64)__float_as_uint(hi) << 32);
}
__device__ __forceinline__ void cp16(u32 dst, const float* src) {
    asm volatile("cp.async.ca.shared.global [%0], [%1], 16;" :: "r"(dst), "l"(src));
}
__device__ __forceinline__ u32 bits8(u64 x, int t) {
    u64 y = (x >> t) & 0x0101010101010101ull;
    return (u32)((y * 0x0102040810204080ull) >> 56);
}

__global__ void __launch_bounds__(NTHREADS, 1)
snn_twin_kernel(const float* __restrict__ state, const float* __restrict__ action,
                const float* __restrict__ W1a, const float* __restrict__ b1a,
                const float* __restrict__ W2a, const float* __restrict__ b2a,
                const float* __restrict__ W3a, const float* __restrict__ b3a,
                const float* __restrict__ W1b, const float* __restrict__ b1b,
                const float* __restrict__ W2b, const float* __restrict__ b2b,
                const float* __restrict__ W3b, const float* __restrict__ b3b,
                float* __restrict__ outp)
{
    if (g_use_tc) return;
    extern __shared__ char smem[];
    float* Wbuf = (float*)smem;
    u8*  maskB  = (u8*)(smem + SMEM_MASKB_OFF);
    u32* planes = (u32*)(smem + SMEM_PLANE_OFF);
    float* Xs   = (float*)(smem + SMEM_XS_OFF);
    float* red  = (float*)(smem + SMEM_RED_OFF);

    const int tid = threadIdx.x;
    const int wid = tid >> 5;
    const int lid = tid & 31;
    const int rg  = tid >> 6;
    const int ci  = tid & 63;
    const int bx  = blockIdx.x;
    const int br  = bx & 1;
    const int m0  = (bx >> 1) * TM;

    const float* W1g = br ? W1b : W1a;
    const float* b1g = br ? b1b : b1a;
    const float* W2g = br ? W2b : W2a;
    const float* b2g = br ? b2b : b2a;
    const float* W3g = br ? W3b : W3a;
    const float* b3g = br ? b3b : b3a;

    u64 acc1[8][4];
    #pragma unroll
    for (int r = 0; r < 8; ++r)
        #pragma unroll
        for (int j = 0; j < 4; ++j) acc1[r][j] = 0ull;

    const int NCH1 = (DD + KB1 - 1) / KB1;
    for (int kb = 0; kb < NCH1; ++kb) {
        const int k0 = kb * KB1;
        #pragma unroll
        for (int q = 0; q < 4; ++q) {
            int idx = q * 2048 + tid * 4;
            int kk = idx >> 9;
            float4 v = make_float4(0.f, 0.f, 0.f, 0.f);
            if (k0 + kk < DD)
                v = *(const float4*)(W1g + (size_t)(k0 + kk) * HH + (idx & 511));
            *(float4*)(Wbuf + idx) = v;
        }
        #pragma unroll
        for (int q = 0; q < 2; ++q) {
            int e = tid * 2 + q;
            int r = e >> 4, kk = e & 15;
            int k = k0 + kk;
            float x = 0.f;
            if (k < NS_)      x = state[(size_t)(m0 + r) * NS_ + k];
            else if (k < DD)  x = action[(size_t)(m0 + r) * NA_ + (k - NS_)];
            Xs[kk * TM + r] = x;
        }
        __syncthreads();
        const int kc = (DD - k0 < KB1) ? (DD - k0) : KB1;
        #pragma unroll 4
        for (int kk = 0; kk < kc; ++kk) {
            const float4 xa = *(const float4*)(Xs + kk * TM + rg * 8);
            const float4 xb = *(const float4*)(Xs + kk * TM + rg * 8 + 4);
            u64 w[4];
            #pragma unroll
            for (int j = 0; j < 4; ++j)
                w[j] = *(const u64*)(Wbuf + kk * HH + 2 * ci + 128 * j);
            const float xr[8] = {xa.x, xa.y, xa.z, xa.w, xb.x, xb.y, xb.z, xb.w};
            #pragma unroll
            for (int r = 0; r < 8; ++r) {
                u64 xp = splat2(xr[r]);
                #pragma unroll
                for (int j = 0; j < 4; ++j) ffma2(acc1[r][j], xp, w[j]);
            }
        }
        __syncthreads();
    }

    #pragma unroll
    for (int j = 0; j < 4; ++j) {
        float2 b1j = *(const float2*)(b1g + 2 * ci + 128 * j);
        #pragma unroll
        for (int h = 0; h < 2; ++h) {
            const int c = 2 * ci + 128 * j + h;
            #pragma unroll
            for (int r = 0; r < 8; ++r) {
                float hv = (h ? hi32(acc1[r][j]) : lo32(acc1[r][j]))
                         + (h ? b1j.y : b1j.x);
                float v = 0.f; u32 mb = 0u;
                #pragma unroll
                for (int t = 0; t < TSTEPS; ++t) {
                    v += hv;
                    if (v >= 1.0f) { mb |= (1u << t); v = 0.f; }
                }
                maskB[(rg * 8 + r) * HH + c] = (u8)mb;
            }
        }
    }
    __syncthreads();

    const u32 wsm = (u32)__cvta_generic_to_shared(Wbuf);
    {
        #pragma unroll
        for (int q = 0; q < 8; ++q) {
            int off = q * 2048 + tid * 4;
            cp16(wsm + (u32)off * 4u, W2g + off);
        }
        asm volatile("cp.async.commit_group;");
    }

    #pragma unroll
    for (int i = 0; i < 2; ++i) {
        const int task = tid * 2 + i;
        const int row = task >> 4;
        const int w   = task & 15;
        const u64* mp = (const u64*)(maskB + row * HH + w * 32);
        const u64 x0 = mp[0], x1 = mp[1], x2 = mp[2], x3 = mp[3];
        #pragma unroll
        for (int t = 0; t < TSTEPS; ++t) {
            u32 word = bits8(x0, t) | (bits8(x1, t) << 8)
                     | (bits8(x2, t) << 16) | (bits8(x3, t) << 24);
            planes[(t * TM + row) * 16 + w] = word;
        }
    }
    __syncthreads();

    const int wrow0 = wid * 4;
    float2 b2p[8], w3p[8];
    #pragma unroll
    for (int m = 0; m < 8; ++m) {
        b2p[m] = *(const float2*)(b2g + 2 * lid + 64 * m);
        w3p[m] = *(const float2*)(W3g + 2 * lid + 64 * m);
    }

    u64 acc[4][8];
    #pragma unroll
    for (int r = 0; r < 4; ++r)
        #pragma unroll
        for (int m = 0; m < 8; ++m) acc[r][m] = 0ull;
    float dv[4] = {0.f, 0.f, 0.f, 0.f};

    float cw = 0.00390625f;
    const int gTotal = TSTEPS * NCH2;

    for (int g = 0; g < gTotal; ++g) {
        const int cb = g & (NCH2 - 1);
        const int t  = g >> 4;

        if (g + 1 < gTotal) {
            const int nb = (cb + 1) & (NCH2 - 1);
            const u32 dst = wsm + (u32)(((g + 1) & 1) * WBUF_FLOATS) * 4u;
            const float* src = W2g + (size_t)nb * KB2 * HH;
            #pragma unroll
            for (int q = 0; q < 8; ++q) {
                int off = q * 2048 + tid * 4;
                cp16(dst + (u32)off * 4u, src + off);
            }
        }
        asm volatile("cp.async.commit_group;");
        asm volatile("cp.async.wait_group 1;");
        __syncthreads();

        const float* Wb = Wbuf + (g & 1) * WBUF_FLOATS;
        const u32* pl = planes + (t * TM + wrow0) * 16 + cb;

        #pragma unroll
        for (int r = 0; r < 4; ++r) {
            u32 mword = pl[r * 16];
            while (mword) {
                const int k = __ffs(mword) - 1;
                mword &= mword - 1;
                const float* wp = Wb + (k << 9) + (lid << 1);
                const u64 w0 = *(const u64*)(wp);
                const u64 w1 = *(const u64*)(wp + 64);
                const u64 w2 = *(const u64*)(wp + 128);
                const u64 w3_ = *(const u64*)(wp + 192);
                const u64 w4 = *(const u64*)(wp + 256);
                const u64 w5 = *(const u64*)(wp + 320);
                const u64 w6 = *(const u64*)(wp + 384);
                const u64 w7 = *(const u64*)(wp + 448);
                add2(acc[r][0], w0); add2(acc[r][1], w1);
                add2(acc[r][2], w2); add2(acc[r][3], w3_);
                add2(acc[r][4], w4); add2(acc[r][5], w5);
                add2(acc[r][6], w6); add2(acc[r][7], w7);
            }
        }

        if (cb == NCH2 - 1) {
            #pragma unroll
            for (int r = 0; r < 4; ++r) {
                #pragma unroll
                for (int m = 0; m < 8; ++m) {
                    float vl = lo32(acc[r][m]) + b2p[m].x;
                    float vh = hi32(acc[r][m]) + b2p[m].y;
                    if (vl >= 1.0f) { dv[r] = fmaf(cw, w3p[m].x, dv[r]); vl = 0.f; }
                    if (vh >= 1.0f) { dv[r] = fmaf(cw, w3p[m].y, dv[r]); vh = 0.f; }
                    acc[r][m] = pack2(vl, vh);
                }
            }
            cw *= 2.0f;
        }
        __syncthreads();
    }

    #pragma unroll
    for (int r = 0; r < 4; ++r) {
        float v = dv[r];
        #pragma unroll
        for (int s = 16; s; s >>= 1) v += __shfl_xor_sync(0xffffffffu, v, s);
        if (lid == 0) red[wrow0 + r] = v;
    }
    __syncthreads();
    if (tid < TM) {
        float q = red[tid] + b3g[0] * (255.0f / 256.0f);
        outp[(size_t)br * 4096 + m0 + tid] = q;
    }
    asm volatile("cp.async.wait_group 0;");
}

// ============================ launch ============================
extern "C" void kernel_launch(void* const* d_in, const int* in_sizes, int n_in,
                              void* d_out, int out_size) {
    (void)in_sizes; (void)n_in; (void)out_size;
    const float* state  = (const float*)d_in[0];
    const float* action = (const float*)d_in[1];
    const float* W1a = (const float*)d_in[2];  const float* b1a = (const float*)d_in[3];
    const float* W2a = (const float*)d_in[4];  const float* b2a = (const float*)d_in[5];
    const float* W3a = (const float*)d_in[6];  const float* b3a = (const float*)d_in[7];
    const float* W1b = (const float*)d_in[8];  const float* b1b = (const float*)d_in[9];
    const float* W2b = (const float*)d_in[10]; const float* b2b = (const float*)d_in[11];
    const float* W3b = (const float*)d_in[12]; const float* b3b = (const float*)d_in[13];
    float* outp = (float*)d_out;

    cudaFuncSetAttribute(gemm_scan_kernel,
                         cudaFuncAttributeMaxDynamicSharedMemorySize, K2_SMEM);
    cudaFuncSetAttribute(snn_twin_kernel,
                         cudaFuncAttributeMaxDynamicSharedMemorySize, SMEM_TOTAL_FB);

    probe_kernel<<<1, 1>>>();
    prep_w2_kernel<<<2048, 256>>>(W2a, W2b);
    mask_kernel<<<128, 512>>>(state, action, W1a, b1a, W1b, b1b);
    gemm_scan_kernel<<<128, 512, K2_SMEM>>>(b2a, b2b, W3a, W3b);
    finish_kernel<<<32, 256>>>(b3a, b3b, outp);
    snn_twin_kernel<<<128, 512, SMEM_TOTAL_FB>>>(
        state, action, W1a, b1a, W2a, b2a, W3a, b3a,
        W1b, b1b, W2b, b2b, W3b, b3b, outp);
}

// round 16
// speedup vs baseline: 1.0542x; 1.0542x over previous
#include <cuda_runtime.h>
#include <cuda_bf16.h>

typedef unsigned int u32;
typedef unsigned long long u64;
typedef unsigned char u8;

#define HH 512
#define NS_ 376
#define NA_ 17
#define DD 393
#define TSTEPS 8

#if defined(__CUDA_ARCH_FEAT_SM100_ALL) || defined(__CUDA_ARCH_FEAT_SM103_ALL)
#define HAS_TC 1
#else
#define HAS_TC 0
#endif

// ------------------------- scratch (device globals) -------------------------
__device__ int           g_use_tc;
__device__ u8            g_masks[2][4096][HH];            // [br][row][k] spike bitmasks (bit t)
// pre-swizzled B tiles: [br][nslice][kchunk][split] -> 32KB SW128 smem image
__device__ __nv_bfloat16 g_w2tiles[2][2][8][3][16384];
__device__ float         g_qpart[2][2][4096];             // [br][nslice][row]

// ============================ probe ============================
__global__ void probe_kernel() {
#if HAS_TC
    g_use_tc = 1;
#else
    g_use_tc = 0;
#endif
}

// ============================ K0: W2 -> bf16 3-way split, pre-swizzled tiles ============================
__global__ void prep_w2_kernel(const float* __restrict__ W2a, const float* __restrict__ W2b)
{
    if (!g_use_tc) return;
    int idx = blockIdx.x * blockDim.x + threadIdx.x;   // 0 .. 524287
    const int kq = idx & 63;
    const int nq = (idx >> 6) & 255;
    const int kc = (idx >> 14) & 7;
    const int ns = (idx >> 17) & 1;
    const int br = idx >> 18;
    const int n = ns * 256 + nq;
    const int k = kc * 64 + kq;
    const float* W2 = br ? W2b : W2a;
    float w = W2[(size_t)k * HH + n];
    __nv_bfloat16 b0 = __float2bfloat16(w);
    float r1 = w - __bfloat162float(b0);
    __nv_bfloat16 b1 = __float2bfloat16(r1);
    float r2 = r1 - __bfloat162float(b1);
    __nv_bfloat16 b2 = __float2bfloat16(r2);
    u32 off = (u32)(nq * 128 + kq * 2);
    off ^= (off >> 3) & 0x70u;
    const u32 e = off >> 1;
    g_w2tiles[br][ns][kc][0][e] = b0;
    g_w2tiles[br][ns][kc][1][e] = b1;
    g_w2tiles[br][ns][kc][2][e] = b2;
}

// ============================ K1: phase1 GEMM + IF masks (tc path) ============================
#define TM1 64
#define KB1 16

__global__ void __launch_bounds__(512, 1)
mask_kernel(const float* __restrict__ state, const float* __restrict__ action,
            const float* __restrict__ W1a, const float* __restrict__ b1a,
            const float* __restrict__ W1b, const float* __restrict__ b1b)
{
    if (!g_use_tc) return;
    __shared__ float Wbuf[KB1 * HH];
    __shared__ float Xs[KB1 * TM1];

    const int tid = threadIdx.x;
    const int rg  = tid >> 6;
    const int ci  = tid & 63;
    const int bx  = blockIdx.x;
    const int br  = bx & 1;
    const int m0  = (bx >> 1) * TM1;

    const float* W1g = br ? W1b : W1a;
    const float* b1g = br ? b1b : b1a;

    u64 acc[8][4];
    #pragma unroll
    for (int r = 0; r < 8; ++r)
        #pragma unroll
        for (int j = 0; j < 4; ++j) acc[r][j] = 0ull;

    const int NCH1 = (DD + KB1 - 1) / KB1;
    for (int kb = 0; kb < NCH1; ++kb) {
        const int k0 = kb * KB1;
        #pragma unroll
        for (int q = 0; q < 4; ++q) {
            int idx = q * 2048 + tid * 4;
            int kk = idx >> 9;
            float4 v = make_float4(0.f, 0.f, 0.f, 0.f);
            if (k0 + kk < DD)
                v = *(const float4*)(W1g + (size_t)(k0 + kk) * HH + (idx & 511));
            *(float4*)(Wbuf + idx) = v;
        }
        #pragma unroll
        for (int q = 0; q < 2; ++q) {
            int e = tid * 2 + q;
            int r = e >> 4, kk = e & 15;
            int k = k0 + kk;
            float x = 0.f;
            if (k < NS_)      x = state[(size_t)(m0 + r) * NS_ + k];
            else if (k < DD)  x = action[(size_t)(m0 + r) * NA_ + (k - NS_)];
            Xs[kk * TM1 + r] = x;
        }
        __syncthreads();
        const int kc = (DD - k0 < KB1) ? (DD - k0) : KB1;
        #pragma unroll 4
        for (int kk = 0; kk < kc; ++kk) {
            const float4 xa = *(const float4*)(Xs + kk * TM1 + rg * 8);
            const float4 xb = *(const float4*)(Xs + kk * TM1 + rg * 8 + 4);
            u64 w[4];
            #pragma unroll
            for (int j = 0; j < 4; ++j)
                w[j] = *(const u64*)(Wbuf + kk * HH + 2 * ci + 128 * j);
            const float xr[8] = {xa.x, xa.y, xa.z, xa.w, xb.x, xb.y, xb.z, xb.w};
            #pragma unroll
            for (int r = 0; r < 8; ++r) {
                u64 xp;
                asm("mov.b64 %0, {%1, %1};" : "=l"(xp) : "f"(xr[r]));
                #pragma unroll
                for (int j = 0; j < 4; ++j)
                    asm("fma.rn.f32x2 %0, %1, %2, %0;" : "+l"(acc[r][j]) : "l"(xp), "l"(w[j]));
            }
        }
        __syncthreads();
    }

    #pragma unroll
    for (int j = 0; j < 4; ++j) {
        float2 b1j = *(const float2*)(b1g + 2 * ci + 128 * j);
        #pragma unroll
        for (int h = 0; h < 2; ++h) {
            const int c = 2 * ci + 128 * j + h;
            #pragma unroll
            for (int r = 0; r < 8; ++r) {
                float hv = (h ? __uint_as_float((u32)(acc[r][j] >> 32))
                              : __uint_as_float((u32)acc[r][j]))
                         + (h ? b1j.y : b1j.x);
                float v = 0.f; u32 mb = 0u;
                #pragma unroll
                for (int t = 0; t < TSTEPS; ++t) {
                    v += hv;
                    if (v >= 1.0f) { mb |= (1u << t); v = 0.f; }
                }
                g_masks[br][m0 + rg * 8 + r][c] = (u8)mb;
            }
        }
    }
}

// ============================ K2: tcgen05 GEMM — 2-deep commit pipeline ============================
#define MMA_IDESC 0x8400490u

#define ABASE    0          /* A tiles: [cpar][t] 16KB -> 64KB */
#define BSL_OFF  65536      /* 4 B slots x 32KB = 128KB */
#define B2_OFF   196608
#define W3_OFF   197632
#define TP_OFF   198656
#define MB_OFF   198664     /* 2 MMA commit mbarriers */
#define LDMB_OFF 198680     /* 4 load mbarriers */
#define K2_SMEM  198720

#define DESC_BASE ((2ull << 61) | (1ull << 46) | (64ull << 32) | (1ull << 16))

#if HAS_TC
__device__ __forceinline__ u32 elect1() {
    u32 p;
    asm volatile("{\n\t.reg .pred p;\n\telect.sync _|p, 0xFFFFFFFF;\n\tselp.b32 %0, 1, 0, p;\n\t}" : "=r"(p));
    return p;
}
__device__ __forceinline__ void mma_f16_ss(u32 d, u64 ad, u64 bd, u32 idesc, u32 en) {
    asm volatile(
        "{\n\t.reg .pred p;\n\tsetp.ne.u32 p, %4, 0;\n\t"
        "tcgen05.mma.cta_group::1.kind::f16 [%0], %1, %2, %3, {%5, %5, %5, %5}, p;\n\t}"
        :: "r"(d), "l"(ad), "l"(bd), "r"(idesc), "r"(en), "r"(0u) : "memory");
}
__device__ __forceinline__ void mbar_wait_bounded(u32 addr, u32 parity) {
    for (int it = 0; it < (1 << 22); ++it) {
        u32 done;
        asm volatile(
            "{\n\t.reg .pred p;\n\t"
            "mbarrier.try_wait.parity.acquire.cta.shared::cta.b64 p, [%1], %2;\n\t"
            "selp.b32 %0, 1, 0, p;\n\t}"
            : "=r"(done) : "r"(addr), "r"(parity) : "memory");
        if (done) return;
    }
}
__device__ __forceinline__ void issue_bulk_tile(u32 dst, const __nv_bfloat16* src, u32 mbar) {
    asm volatile("mbarrier.arrive.expect_tx.shared.b64 _, [%0], %1;"
                 :: "r"(mbar), "r"(32768u) : "memory");
    asm volatile(
        "cp.async.bulk.shared::cta.global.mbarrier::complete_tx::bytes [%0], [%1], %2, [%3];"
        :: "r"(dst), "l"(src), "r"(32768u), "r"(mbar) : "memory");
}
#endif

__global__ void __launch_bounds__(512, 1)
gemm_scan_kernel(const float* __restrict__ b2a, const float* __restrict__ b2b,
                 const float* __restrict__ W3a, const float* __restrict__ W3b)
{
#if HAS_TC
    if (!g_use_tc) return;
    extern __shared__ char sm[];
    const u32 smb = (u32)__cvta_generic_to_shared(sm);

    const int tid = threadIdx.x;
    const int wid = tid >> 5;
    const int lid = tid & 31;
    const int sub = wid & 3;
    const int cs  = wid >> 2;
    const int bx  = blockIdx.x;
    const int br  = bx & 1;
    const int ns  = (bx >> 1) & 1;
    const int mt  = bx >> 2;
    const int m0  = mt * 128;
    const int n0  = ns * 256;

    if (wid == 0)
        asm volatile("tcgen05.alloc.cta_group::1.sync.aligned.shared::cta.b32 [%0], %1;"
                     :: "r"(smb + TP_OFF), "r"(512u) : "memory");
    else
        asm volatile("tcgen05.relinquish_alloc_permit.cta_group::1.sync.aligned;");

    const float* b2g = br ? b2b : b2a;
    const float* w3g = br ? W3b : W3a;
    float* b2s = (float*)(sm + B2_OFF);
    float* w3s = (float*)(sm + W3_OFF);
    if (tid < 256) {
        b2s[tid] = b2g[n0 + tid];
        w3s[tid] = w3g[n0 + tid];
    }
    if (tid == 0) {
        #pragma unroll
        for (int b = 0; b < 2; ++b)
            asm volatile("mbarrier.init.shared.b64 [%0], 1;" :: "r"(smb + MB_OFF + b * 8) : "memory");
        #pragma unroll
        for (int s = 0; s < 4; ++s)
            asm volatile("mbarrier.init.shared.b64 [%0], 1;" :: "r"(smb + LDMB_OFF + s * 8) : "memory");
    }
    __syncthreads();

    u32 tmem;
    asm volatile("ld.shared.b32 %0, [%1];" : "=r"(tmem) : "r"(smb + TP_OFF));

    float v2[64];
    #pragma unroll
    for (int i = 0; i < 64; ++i) v2[i] = 0.f;
    float dv = 0.f;
    float cw = 0.00390625f;     // 2^-8
    int owed[2] = {0, 0};       // outstanding commit per MMA barrier
    int mpar[2] = {0, 0};       // MMA barrier parities
    int lpar[4] = {0, 0, 0, 0}; // load barrier parities

    const int arow = tid >> 2;
    const int apart = tid & 3;
    const u8* mbase = &g_masks[br][m0 + arow][0];

    // prologue: L(0) -> slot0 (chunk0,split0), L(1) -> slot1 (chunk0,split1)
    if (tid == 0) {
        issue_bulk_tile(smb + BSL_OFF,          &g_w2tiles[br][ns][0][0][0], smb + LDMB_OFF);
        issue_bulk_tile(smb + BSL_OFF + 32768u, &g_w2tiles[br][ns][0][1][0], smb + LDMB_OFF + 8);
    }

    for (int cj = 0; cj < 32; ++cj) {
        const int kc = cj & 7;
        const int tp = cj >> 3;
        const int t0 = tp * 2;
        const int t1 = t0 + 1;
        const int cpar = cj & 1;
        const int k0 = kc * 64;
        const u32 abase = smb + (u32)cpar * 32768u;

        // ---- build A tiles for t0/t1 (buffer cpar; chunk cj-2 MMAs proven done via owed chain) ----
        {
            const u64 m8a = *(const u64*)(mbase + k0 + apart * 16);
            const u64 m8b = *(const u64*)(mbase + k0 + apart * 16 + 8);
            #pragma unroll
            for (int p = 0; p < 8; ++p) {
                const u64 src = (p < 4) ? m8a : m8b;
                const int pp = p & 3;
                const u32 be = (u32)(src >> (16 * pp)) & 0xffu;
                const u32 bo = (u32)(src >> (16 * pp + 8)) & 0xffu;
                u32 off = (u32)(arow * 128 + (apart * 16 + 2 * p) * 2);
                off ^= (off >> 3) & 0x70u;
                const u32 v0 = (((be >> t0) & 1u) * 0x3f80u)
                             | ((((bo >> t0) & 1u) * 0x3f80u) << 16);
                const u32 v1 = (((be >> t1) & 1u) * 0x3f80u)
                             | ((((bo >> t1) & 1u) * 0x3f80u) << 16);
                *(u32*)(sm + (abase - smb) + off) = v0;
                *(u32*)(sm + (abase - smb) + 16384 + off) = v1;
            }
        }
        asm volatile("fence.proxy.async.shared::cta;" ::: "memory");
        __syncthreads();

        const u64 aD0 = DESC_BASE | (((u64)(abase >> 4)) & 0x3FFF);
        const u64 aD1 = DESC_BASE | (((u64)((abase + 16384u) >> 4)) & 0x3FFF);

        #pragma unroll
        for (int sp = 0; sp < 3; ++sp) {
            const int j = 3 * cj + sp;
            const int mb = j & 1;
            const int slot = j & 3;

            // ---- wait M(j-2) (same barrier, previous use) ----
            if (owed[mb]) { mbar_wait_bounded(smb + MB_OFF + mb * 8, (u32)mpar[mb]); mpar[mb] ^= 1; owed[mb] = 0; }

            // ---- prefetch L(j+2) (slot safe: owner j-2 proven done just above) ----
            if (tid == 0 && j + 2 < 96) {
                const int jn = j + 2;
                const int cn = (sp == 0) ? cj : (cj + 1);
                const int spn = (sp == 0) ? 2 : (sp - 1);
                const int slotn = jn & 3;
                issue_bulk_tile(smb + BSL_OFF + (u32)slotn * 32768u,
                                &g_w2tiles[br][ns][cn & 7][spn][0],
                                smb + LDMB_OFF + slotn * 8);
            }

            // ---- wait L(j) ----
            mbar_wait_bounded(smb + LDMB_OFF + slot * 8, (u32)lpar[slot]);
            lpar[slot] ^= 1;

            // ---- M(j): 8 MMAs with split sp, commit to barrier mb ----
            if (wid == 0 && elect1()) {
                const u64 bD = DESC_BASE | (((u64)((smb + BSL_OFF + (u32)slot * 32768u) >> 4)) & 0x3FFF);
                #pragma unroll
                for (int ks = 0; ks < 4; ++ks) {
                    const u32 enf = (kc > 0 || ks > 0 || sp > 0) ? 1u : 0u;
                    mma_f16_ss(tmem,       aD0 + ks * 2, bD + ks * 2, MMA_IDESC, enf);
                    mma_f16_ss(tmem + 256, aD1 + ks * 2, bD + ks * 2, MMA_IDESC, enf);
                }
                asm volatile(
                    "tcgen05.commit.cta_group::1.mbarrier::arrive::one.shared::cluster.b64 [%0];"
                    :: "r"(smb + MB_OFF + mb * 8) : "memory");
            }
            owed[mb] = 1;
        }

        // ---- end of K sweep for this timestep pair: drain both barriers, scan ----
        if (kc == 7) {
            #pragma unroll
            for (int b = 0; b < 2; ++b)
                if (owed[b]) { mbar_wait_bounded(smb + MB_OFF + b * 8, (u32)mpar[b]); mpar[b] ^= 1; owed[b] = 0; }
            asm volatile("tcgen05.fence::after_thread_sync;" ::: "memory");
            const int c0 = cs * 64;
            #pragma unroll
            for (int dsel = 0; dsel < 2; ++dsel) {
                #pragma unroll
                for (int h = 0; h < 2; ++h) {
                    u32 p[32];
                    asm volatile(
                        "tcgen05.ld.sync.aligned.32x32b.x32.b32 "
                        "{%0, %1, %2, %3, %4, %5, %6, %7, "
                        " %8, %9, %10, %11, %12, %13, %14, %15, "
                        " %16, %17, %18, %19, %20, %21, %22, %23, "
                        " %24, %25, %26, %27, %28, %29, %30, %31}, [%32];"
                        : "=r"(p[0]), "=r"(p[1]), "=r"(p[2]), "=r"(p[3]),
                          "=r"(p[4]), "=r"(p[5]), "=r"(p[6]), "=r"(p[7]),
                          "=r"(p[8]), "=r"(p[9]), "=r"(p[10]), "=r"(p[11]),
                          "=r"(p[12]), "=r"(p[13]), "=r"(p[14]), "=r"(p[15]),
                          "=r"(p[16]), "=r"(p[17]), "=r"(p[18]), "=r"(p[19]),
                          "=r"(p[20]), "=r"(p[21]), "=r"(p[22]), "=r"(p[23]),
                          "=r"(p[24]), "=r"(p[25]), "=r"(p[26]), "=r"(p[27]),
                          "=r"(p[28]), "=r"(p[29]), "=r"(p[30]), "=r"(p[31])
                        : "r"(tmem + dsel * 256 + c0 + 32 * h));
                    asm volatile("tcgen05.wait::ld.sync.aligned;" ::: "memory");
                    #pragma unroll
                    for (int j2 = 0; j2 < 32; ++j2) {
                        const int col = c0 + 32 * h + j2;
                        float val = v2[h * 32 + j2] + __uint_as_float(p[j2]) + b2s[col];
                        if (val >= 1.0f) { dv = fmaf(cw, w3s[col], dv); val = 0.f; }
                        v2[h * 32 + j2] = val;
                    }
                }
                cw *= 2.0f;
            }
            asm volatile("tcgen05.fence::before_thread_sync;" ::: "memory");
            __syncthreads();
        }
    }

    // ---- dv reduction (dvp aliases A-tile space; MMAs all complete) ----
    float* dvp = (float*)(sm + ABASE);   // [4][128]
    dvp[cs * 128 + sub * 32 + lid] = dv;
    __syncthreads();
    if (tid < 128) {
        float s = dvp[tid] + dvp[128 + tid] + dvp[256 + tid] + dvp[384 + tid];
        g_qpart[br][ns][m0 + tid] = s;
    }
    __syncthreads();
    if (wid == 0)
        asm volatile("tcgen05.dealloc.cta_group::1.sync.aligned.b32 %0, %1;"
                     :: "r"(tmem), "r"(512u));
#else
    return;
#endif
}

// ============================ K3: combine partials ============================
__global__ void finish_kernel(const float* __restrict__ b3a, const float* __restrict__ b3b,
                              float* __restrict__ outp)
{
    if (!g_use_tc) return;
    int idx = blockIdx.x * blockDim.x + threadIdx.x;
    int br = idx >> 12;
    int b = idx & 4095;
    float b3 = (br ? b3b : b3a)[0];
    outp[idx] = g_qpart[br][0][b] + g_qpart[br][1][b] + b3 * (255.0f / 256.0f);
}

// ============================ fallback: round-8 proven sparse kernel ============================
#define TM 64
#define NTHREADS 512
#define KB2 32
#define NCH2 (HH / KB2)
#define WBUF_FLOATS (KB2 * HH)

#define SMEM_MASKB_OFF (2 * WBUF_FLOATS * 4)
#define SMEM_PLANE_OFF (SMEM_MASKB_OFF + TM * HH)
#define SMEM_XS_OFF    SMEM_PLANE_OFF
#define SMEM_RED_OFF   (SMEM_PLANE_OFF + TSTEPS * TM * 16 * 4)
#define SMEM_TOTAL_FB  (SMEM_RED_OFF + TM * 4)

__device__ __forceinline__ void ffma2(u64 &d, u64 a, u64 b) {
    asm("fma.rn.f32x2 %0, %1, %2, %0;" : "+l"(d) : "l"(a), "l"(b));
}
__device__ __forceinline__ void add2(u64 &d, u64 w) {
    asm("add.rn.f32x2 %0, %0, %1;" : "+l"(d) : "l"(w));
}
__device__ __forceinline__ u64 splat2(float x) {
    u64 r; asm("mov.b64 %0, {%1, %1};" : "=l"(r) : "f"(x)); return r;
}
__device__ __forceinline__ float lo32(u64 v) { return __uint_as_float((u32)v); }
__device__ __forceinline__ float hi32(u64 v) { return __uint_as_float((u32)(v >> 32)); }
__device__ __forceinline__ u64 pack2(float lo, float hi) {
    return (u64)__float_as_uint(lo) | ((u64)__float_as_uint(hi) << 32);
}
__device__ __forceinline__ void cp16(u32 dst, const float* src) {
    asm volatile("cp.async.ca.shared.global [%0], [%1], 16;" :: "r"(dst), "l"(src));
}
__device__ __forceinline__ u32 bits8(u64 x, int t) {
    u64 y = (x >> t) & 0x0101010101010101ull;
    return (u32)((y * 0x0102040810204080ull) >> 56);
}

__global__ void __launch_bounds__(NTHREADS, 1)
snn_twin_kernel(const float* __restrict__ state, const float* __restrict__ action,
                const float* __restrict__ W1a, const float* __restrict__ b1a,
                const float* __restrict__ W2a, const float* __restrict__ b2a,
                const float* __restrict__ W3a, const float* __restrict__ b3a,
                const float* __restrict__ W1b, const float* __restrict__ b1b,
                const float* __restrict__ W2b, const float* __restrict__ b2b,
                const float* __restrict__ W3b, const float* __restrict__ b3b,
                float* __restrict__ outp)
{
    if (g_use_tc) return;
    extern __shared__ char smem[];
    float* Wbuf = (float*)smem;
    u8*  maskB  = (u8*)(smem + SMEM_MASKB_OFF);
    u32* planes = (u32*)(smem + SMEM_PLANE_OFF);
    float* Xs   = (float*)(smem + SMEM_XS_OFF);
    float* red  = (float*)(smem + SMEM_RED_OFF);

    const int tid = threadIdx.x;
    const int wid = tid >> 5;
    const int lid = tid & 31;
    const int rg  = tid >> 6;
    const int ci  = tid & 63;
    const int bx  = blockIdx.x;
    const int br  = bx & 1;
    const int m0  = (bx >> 1) * TM;

    const float* W1g = br ? W1b : W1a;
    const float* b1g = br ? b1b : b1a;
    const float* W2g = br ? W2b : W2a;
    const float* b2g = br ? b2b : b2a;
    const float* W3g = br ? W3b : W3a;
    const float* b3g = br ? b3b : b3a;

    u64 acc1[8][4];
    #pragma unroll
    for (int r = 0; r < 8; ++r)
        #pragma unroll
        for (int j = 0; j < 4; ++j) acc1[r][j] = 0ull;

    const int NCH1 = (DD + KB1 - 1) / KB1;
    for (int kb = 0; kb < NCH1; ++kb) {
        const int k0 = kb * KB1;
        #pragma unroll
        for (int q = 0; q < 4; ++q) {
            int idx = q * 2048 + tid * 4;
            int kk = idx >> 9;
            float4 v = make_float4(0.f, 0.f, 0.f, 0.f);
            if (k0 + kk < DD)
                v = *(const float4*)(W1g + (size_t)(k0 + kk) * HH + (idx & 511));
            *(float4*)(Wbuf + idx) = v;
        }
        #pragma unroll
        for (int q = 0; q < 2; ++q) {
            int e = tid * 2 + q;
            int r = e >> 4, kk = e & 15;
            int k = k0 + kk;
            float x = 0.f;
            if (k < NS_)      x = state[(size_t)(m0 + r) * NS_ + k];
            else if (k < DD)  x = action[(size_t)(m0 + r) * NA_ + (k - NS_)];
            Xs[kk * TM + r] = x;
        }
        __syncthreads();
        const int kc = (DD - k0 < KB1) ? (DD - k0) : KB1;
        #pragma unroll 4
        for (int kk = 0; kk < kc; ++kk) {
            const float4 xa = *(const float4*)(Xs + kk * TM + rg * 8);
            const float4 xb = *(const float4*)(Xs + kk * TM + rg * 8 + 4);
            u64 w[4];
            #pragma unroll
            for (int j = 0; j < 4; ++j)
                w[j] = *(const u64*)(Wbuf + kk * HH + 2 * ci + 128 * j);
            const float xr[8] = {xa.x, xa.y, xa.z, xa.w, xb.x, xb.y, xb.z, xb.w};
            #pragma unroll
            for (int r = 0; r < 8; ++r) {
                u64 xp = splat2(xr[r]);
                #pragma unroll
                for (int j = 0; j < 4; ++j) ffma2(acc1[r][j], xp, w[j]);
            }
        }
        __syncthreads();
    }

    #pragma unroll
    for (int j = 0; j < 4; ++j) {
        float2 b1j = *(const float2*)(b1g + 2 * ci + 128 * j);
        #pragma unroll
        for (int h = 0; h < 2; ++h) {
            const int c = 2 * ci + 128 * j + h;
            #pragma unroll
            for (int r = 0; r < 8; ++r) {
                float hv = (h ? hi32(acc1[r][j]) : lo32(acc1[r][j]))
                         + (h ? b1j.y : b1j.x);
                float v = 0.f; u32 mb = 0u;
                #pragma unroll
                for (int t = 0; t < TSTEPS; ++t) {
                    v += hv;
                    if (v >= 1.0f) { mb |= (1u << t); v = 0.f; }
                }
                maskB[(rg * 8 + r) * HH + c] = (u8)mb;
            }
        }
    }
    __syncthreads();

    const u32 wsm = (u32)__cvta_generic_to_shared(Wbuf);
    {
        #pragma unroll
        for (int q = 0; q < 8; ++q) {
            int off = q * 2048 + tid * 4;
            cp16(wsm + (u32)off * 4u, W2g + off);
        }
        asm volatile("cp.async.commit_group;");
    }

    #pragma unroll
    for (int i = 0; i < 2; ++i) {
        const int task = tid * 2 + i;
        const int row = task >> 4;
        const int w   = task & 15;
        const u64* mp = (const u64*)(maskB + row * HH + w * 32);
        const u64 x0 = mp[0], x1 = mp[1], x2 = mp[2], x3 = mp[3];
        #pragma unroll
        for (int t = 0; t < TSTEPS; ++t) {
            u32 word = bits8(x0, t) | (bits8(x1, t) << 8)
                     | (bits8(x2, t) << 16) | (bits8(x3, t) << 24);
            planes[(t * TM + row) * 16 + w] = word;
        }
    }
    __syncthreads();

    const int wrow0 = wid * 4;
    float2 b2p[8], w3p[8];
    #pragma unroll
    for (int m = 0; m < 8; ++m) {
        b2p[m] = *(const float2*)(b2g + 2 * lid + 64 * m);
        w3p[m] = *(const float2*)(W3g + 2 * lid + 64 * m);
    }

    u64 acc[4][8];
    #pragma unroll
    for (int r = 0; r < 4; ++r)
        #pragma unroll
        for (int m = 0; m < 8; ++m) acc[r][m] = 0ull;
    float dv[4] = {0.f, 0.f, 0.f, 0.f};

    float cw = 0.00390625f;
    const int gTotal = TSTEPS * NCH2;

    for (int g = 0; g < gTotal; ++g) {
        const int cb = g & (NCH2 - 1);
        const int t  = g >> 4;

        if (g + 1 < gTotal) {
            const int nb = (cb + 1) & (NCH2 - 1);
            const u32 dst = wsm + (u32)(((g + 1) & 1) * WBUF_FLOATS) * 4u;
            const float* src = W2g + (size_t)nb * KB2 * HH;
            #pragma unroll
            for (int q = 0; q < 8; ++q) {
                int off = q * 2048 + tid * 4;
                cp16(dst + (u32)off * 4u, src + off);
            }
        }
        asm volatile("cp.async.commit_group;");
        asm volatile("cp.async.wait_group 1;");
        __syncthreads();

        const float* Wb = Wbuf + (g & 1) * WBUF_FLOATS;
        const u32* pl = planes + (t * TM + wrow0) * 16 + cb;

        #pragma unroll
        for (int r = 0; r < 4; ++r) {
            u32 mword = pl[r * 16];
            while (mword) {
                const int k = __ffs(mword) - 1;
                mword &= mword - 1;
                const float* wp = Wb + (k << 9) + (lid << 1);
                const u64 w0 = *(const u64*)(wp);
                const u64 w1 = *(const u64*)(wp + 64);
                const u64 w2 = *(const u64*)(wp + 128);
                const u64 w3_ = *(const u64*)(wp + 192);
                const u64 w4 = *(const u64*)(wp + 256);
                const u64 w5 = *(const u64*)(wp + 320);
                const u64 w6 = *(const u64*)(wp + 384);
                const u64 w7 = *(const u64*)(wp + 448);
                add2(acc[r][0], w0); add2(acc[r][1], w1);
                add2(acc[r][2], w2); add2(acc[r][3], w3_);
                add2(acc[r][4], w4); add2(acc[r][5], w5);
                add2(acc[r][6], w6); add2(acc[r][7], w7);
            }
        }

        if (cb == NCH2 - 1) {
            #pragma unroll
            for (int r = 0; r < 4; ++r) {
                #pragma unroll
                for (int m = 0; m < 8; ++m) {
                    float vl = lo32(acc[r][m]) + b2p[m].x;
                    float vh = hi32(acc[r][m]) + b2p[m].y;
                    if (vl >= 1.0f) { dv[r] = fmaf(cw, w3p[m].x, dv[r]); vl = 0.f; }
                    if (vh >= 1.0f) { dv[r] = fmaf(cw, w3p[m].y, dv[r]); vh = 0.f; }
                    acc[r][m] = pack2(vl, vh);
                }
            }
            cw *= 2.0f;
        }
        __syncthreads();
    }

    #pragma unroll
    for (int r = 0; r < 4; ++r) {
        float v = dv[r];
        #pragma unroll
        for (int s = 16; s; s >>= 1) v += __shfl_xor_sync(0xffffffffu, v, s);
        if (lid == 0) red[wrow0 + r] = v;
    }
    __syncthreads();
    if (tid < TM) {
        float q = red[tid] + b3g[0] * (255.0f / 256.0f);
        outp[(size_t)br * 4096 + m0 + tid] = q;
    }
    asm volatile("cp.async.wait_group 0;");
}

// ============================ launch ============================
extern "C" void kernel_launch(void* const* d_in, const int* in_sizes, int n_in,
                              void* d_out, int out_size) {
    (void)in_sizes; (void)n_in; (void)out_size;
    const float* state  = (const float*)d_in[0];
    const float* action = (const float*)d_in[1];
    const float* W1a = (const float*)d_in[2];  const float* b1a = (const float*)d_in[3];
    const float* W2a = (const float*)d_in[4];  const float* b2a = (const float*)d_in[5];
    const float* W3a = (const float*)d_in[6];  const float* b3a = (const float*)d_in[7];
    const float* W1b = (const float*)d_in[8];  const float* b1b = (const float*)d_in[9];
    const float* W2b = (const float*)d_in[10]; const float* b2b = (const float*)d_in[11];
    const float* W3b = (const float*)d_in[12]; const float* b3b = (const float*)d_in[13];
    float* outp = (float*)d_out;

    cudaFuncSetAttribute(gemm_scan_kernel,
                         cudaFuncAttributeMaxDynamicSharedMemorySize, K2_SMEM);
    cudaFuncSetAttribute(snn_twin_kernel,
                         cudaFuncAttributeMaxDynamicSharedMemorySize, SMEM_TOTAL_FB);

    probe_kernel<<<1, 1>>>();
    prep_w2_kernel<<<2048, 256>>>(W2a, W2b);
    mask_kernel<<<128, 512>>>(state, action, W1a, b1a, W1b, b1b);
    gemm_scan_kernel<<<128, 512, K2_SMEM>>>(b2a, b2b, W3a, W3b);
    finish_kernel<<<32, 256>>>(b3a, b3b, outp);
    snn_twin_kernel<<<128, 512, SMEM_TOTAL_FB>>>(
        state, action, W1a, b1a, W2a, b2a, W3a, b3a,
        W1b, b1b, W2b, b2b, W3b, b3b, outp);
}